// round 15
// baseline (speedup 1.0000x reference)
#include <cuda_runtime.h>
#include <cuda_fp16.h>

// ROIPooler: multi-level FPN RoIAlign (torchvision, aligned=True)
// Inputs: x2 [2,256,200,304], x3 [2,256,100,152], x4 [2,256,50,76],
//         x5 [2,256,25,38], boxes [2,256,4]   Output: [512,256,7,7] f32
//
// Overlapped two-phase plan (stream fork/join, graph-capturable):
//   default: T(x5) T(x4) T(x3) --e1-->                T(x2)  G[x2-boxes]  waitE2
//   side:                       waitE1  G[small-boxes] --e2-->
// The small-level gather (~80% of boxes) runs concurrently with the big x2
// transpose; both use mostly disjoint resources (L2-resident gather vs
// DRAM-streaming transpose). Gather = proven HFMA2 channels-last kernel
// with an early-exit level filter.

#define OUTSZ 7
#define SRATE 2
#define NSAMP 14
#define NPTS  196
#define NBINS 49
#define C_TOT 256
#define N_PER_B 256
#define NBOX_TOT 512

#define HW0 (200*304)   // 60800
#define HW1 (100*152)   // 15200
#define HW2 (50*76)     // 3800
#define HW3 (25*38)     // 950
#define PX0 0
#define PX1 (2*HW0)
#define PX2 (PX1 + 2*HW1)
#define PX3 (PX2 + 2*HW2)
#define TOTAL_PX (PX3 + 2*HW3)  // 161500

// 82.7 MB channels-last fp16 scratch (device global: allowed)
__device__ __align__(16) __half g_trans[(size_t)TOTAL_PX * C_TOT];

// ---------------- phase 1: [B,C,HW] f32 -> [B,HW,C] fp16 -------------------
__global__ __launch_bounds__(256)
void transpose_kernel(const float* __restrict__ in, int HW, int pxbase)
{
    __shared__ float tile[64][33];
    const int hw0 = blockIdx.x * 32;
    const int c0  = blockIdx.y * 64;
    const int b   = blockIdx.z;
    const int w    = threadIdx.x >> 5;
    const int lane = threadIdx.x & 31;

    const int hw = hw0 + lane;
    if (hw < HW) {
        #pragma unroll
        for (int i = 0; i < 8; i++) {
            const int row = w * 8 + i;
            tile[row][lane] =
                in[(size_t)(b * C_TOT + c0 + row) * HW + hw];
        }
    }
    __syncthreads();

    __half2* __restrict__ outp = (__half2*)g_trans;
    #pragma unroll
    for (int i = 0; i < 4; i++) {
        const int hwr = w * 4 + i;
        const int hww = hw0 + hwr;
        if (hww < HW) {
            const float a = tile[2 * lane    ][hwr];
            const float c = tile[2 * lane + 1][hwr];
            outp[(size_t)(pxbase + b * HW + hww) * (C_TOT / 2)
                 + (c0 >> 1) + lane] = __floats2half2_rn(a, c);
        }
    }
}

// ---------------- phase 2: gather (HFMA2, level-filtered) ------------------
#define GTHREADS 256
#define CSPLIT 2
#define C_PER 128

__global__ __launch_bounds__(GTHREADS)
void gather_kernel(const float* __restrict__ boxes, float* __restrict__ out,
                   int want_x2)
{
    __shared__ int   s_y0[NSAMP], s_y1[NSAMP], s_x0[NSAMP], s_x1[NSAMP];
    __shared__ float s_fy[NSAMP], s_fx[NSAMP], s_wy[NSAMP], s_wx[NSAMP];
    __shared__ __align__(16) int4  s_o4[NPTS];
    __shared__ __align__(16) uint4 s_wh[NPTS];
    __shared__ __align__(16) float s_out[C_PER * NBINS];

    const int n    = blockIdx.x;
    const int cs   = blockIdx.y;
    const int tid  = threadIdx.x;
    const int w    = tid >> 5;
    const int lane = tid & 31;

    // ---- box params / level select ----
    const float bx1 = __ldg(boxes + n * 4 + 0);
    const float by1 = __ldg(boxes + n * 4 + 1);
    const float bx2 = __ldg(boxes + n * 4 + 2);
    const float by2 = __ldg(boxes + n * 4 + 3);

    const float size = sqrtf((bx2 - bx1) * (by2 - by1));
    float lf = floorf(4.0f + log2f(size / 224.0f + 1e-8f));
    lf = fminf(fmaxf(lf, 2.0f), 5.0f);
    const int lvl = (int)lf - 2;
    if ((lvl == 0) != (want_x2 != 0)) return;   // level filter
    const int b = n / N_PER_B;

    int H, W, HW, pxb;
    float scale;
    switch (lvl) {
        case 0:  H = 200; W = 304; HW = HW0; pxb = PX0; scale = 0.25f;    break;
        case 1:  H = 100; W = 152; HW = HW1; pxb = PX1; scale = 0.125f;   break;
        case 2:  H = 50;  W = 76;  HW = HW2; pxb = PX2; scale = 0.0625f;  break;
        default: H = 25;  W = 38;  HW = HW3; pxb = PX3; scale = 0.03125f; break;
    }
    const int pxbase = pxb + b * HW;

    const float X1 = bx1 * scale - 0.5f;
    const float Y1 = by1 * scale - 0.5f;
    const float bin_w = (bx2 - bx1) * scale / (float)OUTSZ;
    const float bin_h = (by2 - by1) * scale / (float)OUTSZ;

    // ---- stage 1: per-axis tables ----
    if (tid < NSAMP) {
        const int p = tid >> 1;
        const int s = tid & 1;
        const float g = (float)p + ((float)s + 0.5f) / (float)SRATE;
        {
            const float yc = Y1 + g * bin_h;
            const bool valid = (yc >= -1.0f) && (yc <= (float)H);
            float c = fminf(fmaxf(yc, 0.0f), (float)(H - 1));
            const float c0 = floorf(c);
            const int i0 = (int)c0;
            s_y0[tid] = i0;
            s_y1[tid] = min(i0 + 1, H - 1);
            s_fy[tid] = c - c0;
            s_wy[tid] = valid ? 1.0f : 0.0f;
        }
        {
            const float xc = X1 + g * bin_w;
            const bool valid = (xc >= -1.0f) && (xc <= (float)W);
            float c = fminf(fmaxf(xc, 0.0f), (float)(W - 1));
            const float c0 = floorf(c);
            const int i0 = (int)c0;
            s_x0[tid] = i0;
            s_x1[tid] = min(i0 + 1, W - 1);
            s_fx[tid] = c - c0;
            s_wx[tid] = valid ? 1.0f : 0.0f;
        }
    }
    __syncthreads();

    // ---- stage 2: per-point corner offsets + half2-packed weights ----
    for (int pt = tid; pt < NPTS; pt += GTHREADS) {
        const int iy = pt / NSAMP;
        const int ix = pt - iy * NSAMP;
        const float v   = s_wy[iy] * s_wx[ix] * 0.25f;
        const float fy  = s_fy[iy], ofy = 1.0f - fy;
        const float fx  = s_fx[ix], ofx = 1.0f - fx;
        const int r0 = s_y0[iy] * W;
        const int r1 = s_y1[iy] * W;
        const int c0 = s_x0[ix];
        const int c1 = s_x1[ix];
        s_o4[pt] = make_int4(r0 + c0, r0 + c1, r1 + c0, r1 + c1);
        const __half2 w00 = __float2half2_rn(v * ofy * ofx);
        const __half2 w01 = __float2half2_rn(v * ofy * fx);
        const __half2 w10 = __float2half2_rn(v * fy  * ofx);
        const __half2 w11 = __float2half2_rn(v * fy  * fx);
        uint4 packed;
        packed.x = *(const unsigned int*)&w00;
        packed.y = *(const unsigned int*)&w01;
        packed.z = *(const unsigned int*)&w10;
        packed.w = *(const unsigned int*)&w11;
        s_wh[pt] = packed;
    }
    __syncthreads();

    // ---- stage 3: channels-last gather, 2 bins/warp-iter, HFMA2 points ----
    const __half2* __restrict__ base =
        (const __half2*)g_trans + (size_t)pxbase * (C_TOT / 2) + cs * (C_PER / 2);

    for (int rA = w; rA < NBINS; rA += 16) {
        const int  rB   = rA + 8;
        const bool has2 = (rB < NBINS);

        const int phA = rA / OUTSZ, pwA = rA - phA * OUTSZ;
        const int ptA = (2 * phA) * NSAMP + 2 * pwA;
        const int rBs = has2 ? rB : rA;
        const int phB = rBs / OUTSZ, pwB = rBs - phB * OUTSZ;
        const int ptB = (2 * phB) * NSAMP + 2 * pwB;
        const float mB = has2 ? 1.0f : 0.0f;

        float A0 = 0.f, A1 = 0.f, A2 = 0.f, A3 = 0.f;
        float B0 = 0.f, B1 = 0.f, B2 = 0.f, B3 = 0.f;

        #pragma unroll
        for (int sy = 0; sy < SRATE; sy++) {
            #pragma unroll
            for (int sx = 0; sx < SRATE; sx++) {
                const int dpt = sy * NSAMP + sx;
                {
                    const int4  o  = s_o4[ptA + dpt];
                    const uint4 wh = s_wh[ptA + dpt];
                    __half2 acc0 = __float2half2_rn(0.f);
                    __half2 acc1 = __float2half2_rn(0.f);
                    #define PCORN(OFF, WRAW)                                   \
                    {                                                          \
                        const uint2 raw =                                      \
                            ((const uint2*)(base + (size_t)(OFF) * (C_TOT / 2)))[lane]; \
                        const __half2 w2 = *(const __half2*)&(WRAW);           \
                        acc0 = __hfma2(*(const __half2*)&raw.x, w2, acc0);     \
                        acc1 = __hfma2(*(const __half2*)&raw.y, w2, acc1);     \
                    }
                    PCORN(o.x, wh.x)
                    PCORN(o.y, wh.y)
                    PCORN(o.z, wh.z)
                    PCORN(o.w, wh.w)
                    const float2 f0 = __half22float2(acc0);
                    const float2 f1 = __half22float2(acc1);
                    A0 += f0.x; A1 += f0.y; A2 += f1.x; A3 += f1.y;
                }
                {
                    const int4  o  = s_o4[ptB + dpt];
                    const uint4 wh = s_wh[ptB + dpt];
                    __half2 acc0 = __float2half2_rn(0.f);
                    __half2 acc1 = __float2half2_rn(0.f);
                    PCORN(o.x, wh.x)
                    PCORN(o.y, wh.y)
                    PCORN(o.z, wh.z)
                    PCORN(o.w, wh.w)
                    #undef PCORN
                    const float2 f0 = __half22float2(acc0);
                    const float2 f1 = __half22float2(acc1);
                    B0 += f0.x * mB; B1 += f0.y * mB;
                    B2 += f1.x * mB; B3 += f1.y * mB;
                }
            }
        }

        const int cl = lane * 4;
        s_out[(cl + 0) * NBINS + rA] = A0;
        s_out[(cl + 1) * NBINS + rA] = A1;
        s_out[(cl + 2) * NBINS + rA] = A2;
        s_out[(cl + 3) * NBINS + rA] = A3;
        if (has2) {
            s_out[(cl + 0) * NBINS + rB] = B0;
            s_out[(cl + 1) * NBINS + rB] = B1;
            s_out[(cl + 2) * NBINS + rB] = B2;
            s_out[(cl + 3) * NBINS + rB] = B3;
        }
    }
    __syncthreads();

    // ---- flush: out slice for (box, cs) is linear 128*49 floats ----
    float4* __restrict__ oc =
        (float4*)(out + (size_t)n * (C_TOT * NBINS) + (size_t)cs * (C_PER * NBINS));
    const float4* __restrict__ so = (const float4*)s_out;
    for (int i = tid; i < (C_PER * NBINS) / 4; i += GTHREADS)
        oc[i] = so[i];
}

extern "C" void kernel_launch(void* const* d_in, const int* in_sizes, int n_in,
                              void* d_out, int out_size)
{
    const float* x2    = (const float*)d_in[0];
    const float* x3    = (const float*)d_in[1];
    const float* x4    = (const float*)d_in[2];
    const float* x5    = (const float*)d_in[3];
    const float* boxes = (const float*)d_in[4];
    float* out = (float*)d_out;

    // lazy one-time stream/event creation (first call = correctness run,
    // which is NOT captured; capture replays see identical launch work)
    static cudaStream_t s1 = nullptr;
    static cudaEvent_t  e1 = nullptr, e2 = nullptr;
    if (s1 == nullptr) {
        cudaStreamCreateWithFlags(&s1, cudaStreamNonBlocking);
        cudaEventCreateWithFlags(&e1, cudaEventDisableTiming);
        cudaEventCreateWithFlags(&e2, cudaEventDisableTiming);
    }

    // small-level transposes first (x5, x4, x3)
    transpose_kernel<<<dim3((HW3 + 31) / 32, 4, 2), 256>>>(x5, HW3, PX3);
    transpose_kernel<<<dim3((HW2 + 31) / 32, 4, 2), 256>>>(x4, HW2, PX2);
    transpose_kernel<<<dim3((HW1 + 31) / 32, 4, 2), 256>>>(x3, HW1, PX1);
    cudaEventRecord(e1, 0);

    // side stream: gather for small-level boxes, overlapping x2 transpose
    cudaStreamWaitEvent(s1, e1, 0);
    gather_kernel<<<dim3(NBOX_TOT, CSPLIT), GTHREADS, 0, s1>>>(boxes, out, 0);
    cudaEventRecord(e2, s1);

    // default stream: big x2 transpose, then x2-box gather
    transpose_kernel<<<dim3((HW0 + 31) / 32, 4, 2), 256>>>(x2, HW0, PX0);
    gather_kernel<<<dim3(NBOX_TOT, CSPLIT), GTHREADS>>>(boxes, out, 1);

    // join side stream back into the captured stream
    cudaStreamWaitEvent(0, e2, 0);
}

// round 17
// speedup vs baseline: 1.4494x; 1.4494x over previous
#include <cuda_runtime.h>
#include <cuda_fp16.h>

// ROIPooler: multi-level FPN RoIAlign (torchvision, aligned=True)
// Inputs: x2 [2,256,200,304], x3 [2,256,100,152], x4 [2,256,50,76],
//         x5 [2,256,25,38], boxes [2,256,4]   Output: [512,256,7,7] f32
//
// x2-level boxes (~15%) are gathered DIRECTLY from the channel-major f32
// input (no transpose dependency) on a side stream that forks from the
// captured stream via an event at t=0 (legal capture fork — R16's missing
// piece). Small levels (x3,x4,x5; ~85% of boxes) are transposed to a
// 20.4 MB channels-last fp16 scratch (one merged launch, L2-resident) and
// gathered with the proven HFMA2 channels-last kernel.

#define OUTSZ 7
#define SRATE 2
#define NSAMP 14
#define NPTS  196
#define NBINS 49
#define C_TOT 256
#define N_PER_B 256
#define NBOX_TOT 512

#define HW0 (200*304)   // x2: 60800 (NOT transposed)
#define HW1 (100*152)   // x3: 15200
#define HW2 (50*76)     // x4: 3800
#define HW3 (25*38)     // x5: 950
// scratch holds ONLY x3,x4,x5 (channels-last fp16): 39900 px = 20.4 MB
#define PXB1 0
#define PXB2 (PXB1 + 2*HW1)
#define PXB3 (PXB2 + 2*HW2)
#define TOTAL_PX_S (PXB3 + 2*HW3)  // 39900

// merged small-transpose tile table (32 hw each), order x5, x4, x3
#define T3 ((HW3 + 31) / 32)    // 30
#define T2 ((HW2 + 31) / 32)    // 119
#define T1 ((HW1 + 31) / 32)    // 475
#define SB2 T3                  // 30
#define SB1 (SB2 + T2)          // 149
#define STILES (SB1 + T1)       // 624

__device__ __align__(16) __half g_trans[(size_t)TOTAL_PX_S * C_TOT];

// ---------------- merged small-level transpose -----------------------------
__global__ __launch_bounds__(256)
void transpose_small_kernel(const float* __restrict__ x3,
                            const float* __restrict__ x4,
                            const float* __restrict__ x5)
{
    __shared__ float tile[64][33];
    const int t = blockIdx.x;
    const float* in;
    int HW, pxbase, tb;
    if (t < SB2)      { in = x5; HW = HW3; pxbase = PXB3; tb = 0;   }
    else if (t < SB1) { in = x4; HW = HW2; pxbase = PXB2; tb = SB2; }
    else              { in = x3; HW = HW1; pxbase = PXB1; tb = SB1; }

    const int hw0 = (t - tb) * 32;
    const int c0  = blockIdx.y * 64;
    const int b   = blockIdx.z;
    const int w    = threadIdx.x >> 5;
    const int lane = threadIdx.x & 31;

    const int hw = hw0 + lane;
    if (hw < HW) {
        #pragma unroll
        for (int i = 0; i < 8; i++) {
            const int row = w * 8 + i;
            tile[row][lane] =
                in[(size_t)(b * C_TOT + c0 + row) * HW + hw];
        }
    }
    __syncthreads();

    __half2* __restrict__ outp = (__half2*)g_trans;
    #pragma unroll
    for (int i = 0; i < 4; i++) {
        const int hwr = w * 4 + i;
        const int hww = hw0 + hwr;
        if (hww < HW) {
            const float a = tile[2 * lane    ][hwr];
            const float c = tile[2 * lane + 1][hwr];
            outp[(size_t)(pxbase + b * HW + hww) * (C_TOT / 2)
                 + (c0 >> 1) + lane] = __floats2half2_rn(a, c);
        }
    }
}

// ---------------- level select helper (identical math everywhere) ----------
__device__ __forceinline__ int box_level(float bx1, float by1,
                                         float bx2, float by2)
{
    const float size = sqrtf((bx2 - bx1) * (by2 - by1));
    float lf = floorf(4.0f + log2f(size / 224.0f + 1e-8f));
    lf = fminf(fmaxf(lf, 2.0f), 5.0f);
    return (int)lf - 2;
}

// ---------------- small-level gather (HFMA2 channels-last) -----------------
#define GTHREADS 256
#define CSPLIT 2
#define C_PER 128

__global__ __launch_bounds__(GTHREADS)
void gather_small_kernel(const float* __restrict__ boxes,
                         float* __restrict__ out)
{
    __shared__ int   s_y0[NSAMP], s_y1[NSAMP], s_x0[NSAMP], s_x1[NSAMP];
    __shared__ float s_fy[NSAMP], s_fx[NSAMP], s_wy[NSAMP], s_wx[NSAMP];
    __shared__ __align__(16) int4  s_o4[NPTS];
    __shared__ __align__(16) uint4 s_wh[NPTS];
    __shared__ __align__(16) float s_out[C_PER * NBINS];

    const int n    = blockIdx.x;
    const int cs   = blockIdx.y;
    const int tid  = threadIdx.x;
    const int w    = tid >> 5;
    const int lane = tid & 31;

    const float bx1 = __ldg(boxes + n * 4 + 0);
    const float by1 = __ldg(boxes + n * 4 + 1);
    const float bx2 = __ldg(boxes + n * 4 + 2);
    const float by2 = __ldg(boxes + n * 4 + 3);

    const int lvl = box_level(bx1, by1, bx2, by2);
    if (lvl == 0) return;                       // x2 boxes: direct kernel
    const int b = n / N_PER_B;

    int H, W, HW, pxb;
    float scale;
    switch (lvl) {
        case 1:  H = 100; W = 152; HW = HW1; pxb = PXB1; scale = 0.125f;   break;
        case 2:  H = 50;  W = 76;  HW = HW2; pxb = PXB2; scale = 0.0625f;  break;
        default: H = 25;  W = 38;  HW = HW3; pxb = PXB3; scale = 0.03125f; break;
    }
    const int pxbase = pxb + b * HW;

    const float X1 = bx1 * scale - 0.5f;
    const float Y1 = by1 * scale - 0.5f;
    const float bin_w = (bx2 - bx1) * scale / (float)OUTSZ;
    const float bin_h = (by2 - by1) * scale / (float)OUTSZ;

    if (tid < NSAMP) {
        const int p = tid >> 1;
        const int s = tid & 1;
        const float g = (float)p + ((float)s + 0.5f) / (float)SRATE;
        {
            const float yc = Y1 + g * bin_h;
            const bool valid = (yc >= -1.0f) && (yc <= (float)H);
            float c = fminf(fmaxf(yc, 0.0f), (float)(H - 1));
            const float c0 = floorf(c);
            const int i0 = (int)c0;
            s_y0[tid] = i0;
            s_y1[tid] = min(i0 + 1, H - 1);
            s_fy[tid] = c - c0;
            s_wy[tid] = valid ? 1.0f : 0.0f;
        }
        {
            const float xc = X1 + g * bin_w;
            const bool valid = (xc >= -1.0f) && (xc <= (float)W);
            float c = fminf(fmaxf(xc, 0.0f), (float)(W - 1));
            const float c0 = floorf(c);
            const int i0 = (int)c0;
            s_x0[tid] = i0;
            s_x1[tid] = min(i0 + 1, W - 1);
            s_fx[tid] = c - c0;
            s_wx[tid] = valid ? 1.0f : 0.0f;
        }
    }
    __syncthreads();

    for (int pt = tid; pt < NPTS; pt += GTHREADS) {
        const int iy = pt / NSAMP;
        const int ix = pt - iy * NSAMP;
        const float v   = s_wy[iy] * s_wx[ix] * 0.25f;
        const float fy  = s_fy[iy], ofy = 1.0f - fy;
        const float fx  = s_fx[ix], ofx = 1.0f - fx;
        const int r0 = s_y0[iy] * W;
        const int r1 = s_y1[iy] * W;
        const int c0 = s_x0[ix];
        const int c1 = s_x1[ix];
        s_o4[pt] = make_int4(r0 + c0, r0 + c1, r1 + c0, r1 + c1);
        const __half2 w00 = __float2half2_rn(v * ofy * ofx);
        const __half2 w01 = __float2half2_rn(v * ofy * fx);
        const __half2 w10 = __float2half2_rn(v * fy  * ofx);
        const __half2 w11 = __float2half2_rn(v * fy  * fx);
        uint4 packed;
        packed.x = *(const unsigned int*)&w00;
        packed.y = *(const unsigned int*)&w01;
        packed.z = *(const unsigned int*)&w10;
        packed.w = *(const unsigned int*)&w11;
        s_wh[pt] = packed;
    }
    __syncthreads();

    const __half2* __restrict__ base =
        (const __half2*)g_trans + (size_t)pxbase * (C_TOT / 2) + cs * (C_PER / 2);

    for (int rA = w; rA < NBINS; rA += 16) {
        const int  rB   = rA + 8;
        const bool has2 = (rB < NBINS);

        const int phA = rA / OUTSZ, pwA = rA - phA * OUTSZ;
        const int ptA = (2 * phA) * NSAMP + 2 * pwA;
        const int rBs = has2 ? rB : rA;
        const int phB = rBs / OUTSZ, pwB = rBs - phB * OUTSZ;
        const int ptB = (2 * phB) * NSAMP + 2 * pwB;
        const float mB = has2 ? 1.0f : 0.0f;

        float A0 = 0.f, A1 = 0.f, A2 = 0.f, A3 = 0.f;
        float B0 = 0.f, B1 = 0.f, B2 = 0.f, B3 = 0.f;

        #pragma unroll
        for (int sy = 0; sy < SRATE; sy++) {
            #pragma unroll
            for (int sx = 0; sx < SRATE; sx++) {
                const int dpt = sy * NSAMP + sx;
                {
                    const int4  o  = s_o4[ptA + dpt];
                    const uint4 wh = s_wh[ptA + dpt];
                    __half2 acc0 = __float2half2_rn(0.f);
                    __half2 acc1 = __float2half2_rn(0.f);
                    #define PCORN(OFF, WRAW)                                   \
                    {                                                          \
                        const uint2 raw =                                      \
                            ((const uint2*)(base + (size_t)(OFF) * (C_TOT / 2)))[lane]; \
                        const __half2 w2 = *(const __half2*)&(WRAW);           \
                        acc0 = __hfma2(*(const __half2*)&raw.x, w2, acc0);     \
                        acc1 = __hfma2(*(const __half2*)&raw.y, w2, acc1);     \
                    }
                    PCORN(o.x, wh.x)
                    PCORN(o.y, wh.y)
                    PCORN(o.z, wh.z)
                    PCORN(o.w, wh.w)
                    const float2 f0 = __half22float2(acc0);
                    const float2 f1 = __half22float2(acc1);
                    A0 += f0.x; A1 += f0.y; A2 += f1.x; A3 += f1.y;
                }
                {
                    const int4  o  = s_o4[ptB + dpt];
                    const uint4 wh = s_wh[ptB + dpt];
                    __half2 acc0 = __float2half2_rn(0.f);
                    __half2 acc1 = __float2half2_rn(0.f);
                    PCORN(o.x, wh.x)
                    PCORN(o.y, wh.y)
                    PCORN(o.z, wh.z)
                    PCORN(o.w, wh.w)
                    #undef PCORN
                    const float2 f0 = __half22float2(acc0);
                    const float2 f1 = __half22float2(acc1);
                    B0 += f0.x * mB; B1 += f0.y * mB;
                    B2 += f1.x * mB; B3 += f1.y * mB;
                }
            }
        }

        const int cl = lane * 4;
        s_out[(cl + 0) * NBINS + rA] = A0;
        s_out[(cl + 1) * NBINS + rA] = A1;
        s_out[(cl + 2) * NBINS + rA] = A2;
        s_out[(cl + 3) * NBINS + rA] = A3;
        if (has2) {
            s_out[(cl + 0) * NBINS + rB] = B0;
            s_out[(cl + 1) * NBINS + rB] = B1;
            s_out[(cl + 2) * NBINS + rB] = B2;
            s_out[(cl + 3) * NBINS + rB] = B3;
        }
    }
    __syncthreads();

    float4* __restrict__ oc =
        (float4*)(out + (size_t)n * (C_TOT * NBINS) + (size_t)cs * (C_PER * NBINS));
    const float4* __restrict__ so = (const float4*)s_out;
    for (int i = tid; i < (C_PER * NBINS) / 4; i += GTHREADS)
        oc[i] = so[i];
}

// ---------------- x2-level direct gather (channel-major f32, R2-style) -----
__global__ __launch_bounds__(256)
void gather_x2_kernel(const float* __restrict__ x2,
                      const float* __restrict__ boxes,
                      float* __restrict__ out)
{
    __shared__ int   s_y0[NSAMP], s_y1[NSAMP], s_x0[NSAMP], s_x1[NSAMP];
    __shared__ float s_fy[NSAMP], s_fx[NSAMP], s_wy[NSAMP], s_wx[NSAMP];
    __shared__ __align__(16) int4   s_o4[NPTS];
    __shared__ __align__(16) float4 s_w4[NPTS];

    const int n   = blockIdx.x;
    const int tid = threadIdx.x;

    const float bx1 = __ldg(boxes + n * 4 + 0);
    const float by1 = __ldg(boxes + n * 4 + 1);
    const float bx2 = __ldg(boxes + n * 4 + 2);
    const float by2 = __ldg(boxes + n * 4 + 3);

    if (box_level(bx1, by1, bx2, by2) != 0) return;   // only x2 boxes
    const int b = n / N_PER_B;

    const int H = 200, W = 304, HW = HW0;
    const float scale = 0.25f;
    const float* __restrict__ feat = x2 + (size_t)b * C_TOT * HW;

    const float X1 = bx1 * scale - 0.5f;
    const float Y1 = by1 * scale - 0.5f;
    const float bin_w = (bx2 - bx1) * scale / (float)OUTSZ;
    const float bin_h = (by2 - by1) * scale / (float)OUTSZ;

    if (tid < NSAMP) {
        const int p = tid >> 1;
        const int s = tid & 1;
        const float g = (float)p + ((float)s + 0.5f) / (float)SRATE;
        {
            const float yc = Y1 + g * bin_h;
            const bool valid = (yc >= -1.0f) && (yc <= (float)H);
            float c = fminf(fmaxf(yc, 0.0f), (float)(H - 1));
            const float c0 = floorf(c);
            const int i0 = (int)c0;
            s_y0[tid] = i0;
            s_y1[tid] = min(i0 + 1, H - 1);
            s_fy[tid] = c - c0;
            s_wy[tid] = valid ? 1.0f : 0.0f;
        }
        {
            const float xc = X1 + g * bin_w;
            const bool valid = (xc >= -1.0f) && (xc <= (float)W);
            float c = fminf(fmaxf(xc, 0.0f), (float)(W - 1));
            const float c0 = floorf(c);
            const int i0 = (int)c0;
            s_x0[tid] = i0;
            s_x1[tid] = min(i0 + 1, W - 1);
            s_fx[tid] = c - c0;
            s_wx[tid] = valid ? 1.0f : 0.0f;
        }
    }
    __syncthreads();

    for (int pt = tid; pt < NPTS; pt += 256) {
        const int iy = pt / NSAMP;
        const int ix = pt - iy * NSAMP;
        const float v   = s_wy[iy] * s_wx[ix] * 0.25f;
        const float fy  = s_fy[iy], ofy = 1.0f - fy;
        const float fx  = s_fx[ix], ofx = 1.0f - fx;
        const int r0 = s_y0[iy] * W;
        const int r1 = s_y1[iy] * W;
        const int c0 = s_x0[ix];
        const int c1 = s_x1[ix];
        s_o4[pt] = make_int4(r0 + c0, r0 + c1, r1 + c0, r1 + c1);
        s_w4[pt] = make_float4(v * ofy * ofx, v * ofy * fx,
                               v * fy  * ofx, v * fy  * fx);
    }
    __syncthreads();

    const int cbase = blockIdx.y * 64;
    for (int idx = tid; idx < 64 * NBINS; idx += 256) {
        const int cq = idx / NBINS;
        const int r  = idx - cq * NBINS;
        const int ph = r / OUTSZ;
        const int pw = r - ph * OUTSZ;
        const int c  = cbase + cq;

        const float* __restrict__ fc = feat + (size_t)c * HW;
        const int ptbase = (2 * ph) * NSAMP + 2 * pw;

        float acc = 0.0f;
        #pragma unroll
        for (int sy = 0; sy < SRATE; sy++) {
            #pragma unroll
            for (int sx = 0; sx < SRATE; sx++) {
                const int pt = ptbase + sy * NSAMP + sx;
                const int4   o  = s_o4[pt];
                const float4 wt = s_w4[pt];
                acc = fmaf(__ldg(fc + o.x), wt.x, acc);
                acc = fmaf(__ldg(fc + o.y), wt.y, acc);
                acc = fmaf(__ldg(fc + o.z), wt.z, acc);
                acc = fmaf(__ldg(fc + o.w), wt.w, acc);
            }
        }
        out[(size_t)n * (C_TOT * NBINS) + (size_t)c * NBINS + r] = acc;
    }
}

extern "C" void kernel_launch(void* const* d_in, const int* in_sizes, int n_in,
                              void* d_out, int out_size)
{
    const float* x2    = (const float*)d_in[0];
    const float* x3    = (const float*)d_in[1];
    const float* x4    = (const float*)d_in[2];
    const float* x5    = (const float*)d_in[3];
    const float* boxes = (const float*)d_in[4];
    float* out = (float*)d_out;

    static cudaStream_t s1 = nullptr;
    static cudaEvent_t  e0 = nullptr, e2 = nullptr;
    if (s1 == nullptr) {
        cudaStreamCreateWithFlags(&s1, cudaStreamNonBlocking);
        cudaEventCreateWithFlags(&e0, cudaEventDisableTiming);
        cudaEventCreateWithFlags(&e2, cudaEventDisableTiming);
    }

    // legal capture fork: side stream waits an event recorded on stream 0
    cudaEventRecord(e0, 0);
    cudaStreamWaitEvent(s1, e0, 0);

    // side stream: x2-box direct gather (no data deps, starts immediately)
    gather_x2_kernel<<<dim3(NBOX_TOT, 4), 256, 0, s1>>>(x2, boxes, out);
    cudaEventRecord(e2, s1);

    // main stream: merged small transpose -> small-box gather
    transpose_small_kernel<<<dim3(STILES, 4, 2), 256>>>(x3, x4, x5);
    gather_small_kernel<<<dim3(NBOX_TOT, CSPLIT), GTHREADS>>>(boxes, out);

    // join
    cudaStreamWaitEvent(0, e2, 0);
}